// round 5
// baseline (speedup 1.0000x reference)
#include <cuda_runtime.h>
#include <cstdint>
#include <cstddef>

#define BB 1024
#define TT 1024
#define NN 34
#define BPB 2                      // batches per block (forward)
#define FWD_THREADS (BPB * NN)     // 68 threads
#define FWD_BLOCKS  592            // 4 CTAs per SM

// Score history: row r of batch b holds S_{r-1} (row 0 = init). [B][T+1][N]
__device__ float g_S[(size_t)BB * (TT + 1) * NN];
__device__ int g_idx[BB];

__device__ __forceinline__ unsigned long long addx2(unsigned long long a, unsigned long long b) {
    unsigned long long r;
    asm("add.rn.f32x2 %0, %1, %2;" : "=l"(r) : "l"(a), "l"(b));
    return r;
}
__device__ __forceinline__ unsigned long long packff(float f) {
    unsigned long long r; unsigned u = __float_as_uint(f);
    asm("mov.b64 %0, {%1, %1};" : "=l"(r) : "r"(u));
    return r;
}
__device__ __forceinline__ void unpk(unsigned long long v, float& lo, float& hi) {
    unsigned a, b;
    asm("mov.b64 {%0, %1}, %2;" : "=r"(a), "=r"(b) : "l"(v));
    lo = __uint_as_float(a); hi = __uint_as_float(b);
}

__global__ __launch_bounds__(FWD_THREADS)
void viterbi_fwd(const float* __restrict__ feat,
                 const float* __restrict__ trans,
                 float* __restrict__ out)
{
    const int tid = threadIdx.x;
    const int bl  = tid / NN;
    const int j   = tid % NN;
    int b = blockIdx.x * BPB + bl;
    if (b >= BB) b = BB - 1;       // tail CTAs duplicate batch 1023: identical writes, benign

    __shared__ __align__(16) float sc[2][BPB][36];
    __shared__ float tend[NN];
    __shared__ float fin[BPB][NN];

    unsigned long long trp[17];
#pragma unroll
    for (int i = 0; i < 17; i++) {
        unsigned lo = __float_as_uint(trans[j * NN + 2 * i]);
        unsigned hi = __float_as_uint(trans[j * NN + 2 * i + 1]);
        asm("mov.b64 %0, {%1, %2};" : "=l"(trp[i]) : "r"(lo), "r"(hi));
    }
    if (tid < NN) tend[tid] = trans[(NN - 1) * NN + tid];

    const float init = (j == NN - 2) ? 0.0f : -6969.0f;
    sc[0][bl][j] = init;
    g_S[((size_t)b * (TT + 1)) * NN + j] = init;
    __syncthreads();

    const size_t fbase = (size_t)b * ((size_t)TT * NN) + j;
    const float* fp = feat + fbase;
    float* sp_out = g_S + ((size_t)b * (TT + 1) + 1) * NN + j;

    float fring[4];
#pragma unroll
    for (int u = 0; u < 4; u++) fring[u] = __ldg(fp + (size_t)u * NN);
    fp += (size_t)4 * NN;

    int cur = 0;
#pragma unroll 1
    for (int tb = 0; tb < TT; tb += 4) {
#pragma unroll
        for (int u = 0; u < 4; u++) {
            const int t = tb + u;
            float f = fring[u];
            float fn = 0.0f;
            if (t + 4 < TT) fn = __ldg(fp);
            fp += NN;
            fring[u] = fn;

            const ulonglong2* sp2 = (const ulonglong2*)&sc[cur][bl][0];
            unsigned long long ff = packff(f);

            float m[NN];
#pragma unroll
            for (int i = 0; i < 8; i++) {
                ulonglong2 q = sp2[i];
                unsigned long long v0 = addx2(addx2(q.x, ff), trp[2 * i]);
                unsigned long long v1 = addx2(addx2(q.y, ff), trp[2 * i + 1]);
                unpk(v0, m[4 * i], m[4 * i + 1]);
                unpk(v1, m[4 * i + 2], m[4 * i + 3]);
            }
            {
                unsigned long long q = *(const unsigned long long*)&sc[cur][bl][32];
                unsigned long long v = addx2(addx2(q, ff), trp[16]);
                unpk(v, m[32], m[33]);
            }
#pragma unroll
            for (int s = 1; s < NN; s <<= 1)
#pragma unroll
                for (int k = 0; k + s < NN; k += (s << 1))
                    m[k] = fmaxf(m[k], m[k + s]);

            sc[cur ^ 1][bl][j] = m[0];
            *sp_out = m[0];
            sp_out += NN;
            cur ^= 1;
            __syncthreads();
        }
    }

    fin[bl][j] = sc[cur][bl][j] + tend[j];
    __syncthreads();
    if (j == 0) {
        float bm = -3.4e38f; int bi = 0;
#pragma unroll
        for (int k = 0; k < NN; k++) {
            float v = fin[bl][k];
            if (v > bm) { bm = v; bi = k; }
        }
        out[b] = bm;
        g_idx[b] = bi;
    }
}

// Backtrack via equality matching. Warp per batch; lane l<17 owns candidate
// states 2l, 2l+1 (float2 ring, 16 ring floats — no spill). Target row S_t is
// the previous iteration's candidate pair, carried in Pv (no extra ring).
__global__ __launch_bounds__(256)
void viterbi_back(const float* __restrict__ feat,
                  const float* __restrict__ trans,
                  float* __restrict__ out)
{
    __shared__ float tr[NN * NN];
    for (int i = threadIdx.x; i < NN * NN; i += blockDim.x) tr[i] = trans[i];
    __syncthreads();

    const int b = blockIdx.x * 8 + (threadIdx.x >> 5);
    const int l = threadIdx.x & 31;
    const unsigned FULL = 0xffffffffu;
    const bool own = (l < 17);

    int j = g_idx[b];
    float* path = out + BB + (size_t)b * (TT + 1);
    if (l == 0) path[TT] = (float)j;

    const float* Sbase = g_S + (size_t)b * (TT + 1) * NN;   // row r = S_{r-1}
    const float* Fbase = feat + (size_t)b * TT * NN;

    // Pv: pair layout of target row (initially row TT = S_{TT-1})
    float2 Pv = own ? *(const float2*)(Sbase + (size_t)TT * NN + 2 * l)
                    : make_float2(0.f, 0.f);

    // 4-deep rings, slot = t & 3
    float2 Sv[4]; float Fa[4], Fb[4];
#pragma unroll
    for (int u = 0; u < 4; u++) {
        int t = TT - 1 - u;
        const int s = t & 3;
        const float* Srow = Sbase + (size_t)t * NN;   // S_{t-1} (candidates)
        const float* Frow = Fbase + (size_t)t * NN;
        Sv[s] = own ? *(const float2*)(Srow + 2 * l) : make_float2(0.f, 0.f);
        Fa[s] = __ldg(Frow + l);
        Fb[s] = __ldg(Frow + 32 + (l & 1));
    }

#pragma unroll 1
    for (int tb = TT - 1; tb >= 0; tb -= 4) {
#pragma unroll
        for (int u = 0; u < 4; u++) {
            const int t = tb - u;
            const int s = t & 3;

            // target = S_t[j] from Pv pair layout (lane j>>1, comp j&1)
            float t0 = __shfl_sync(FULL, Pv.x, j >> 1);
            float t1 = __shfl_sync(FULL, Pv.y, j >> 1);
            float tgt = (j & 1) ? t1 : t0;
            // f = feat[t][j]
            float f1 = __shfl_sync(FULL, Fa[s], j & 31);
            float f2 = __shfl_sync(FULL, Fb[s], j & 1);
            float f  = (j < 32) ? f1 : f2;

            float2 tv = own ? *(const float2*)(tr + j * NN + 2 * l)
                            : make_float2(0.f, 0.f);
            float c0 = (Sv[s].x + f) + tv.x;     // same association as forward
            float c1 = (Sv[s].y + f) + tv.y;
            unsigned m0 = __ballot_sync(FULL, own && (c0 == tgt));
            unsigned m1 = __ballot_sync(FULL, own && (c1 == tgt));
            int a0 = m0 ? 2 * (__ffs(m0) - 1)     : 1000;
            int a1 = m1 ? 2 * (__ffs(m1) - 1) + 1 : 1000;
            j = a0 < a1 ? a0 : a1;               // smallest k = first maximizer
            if (l == 0) path[t] = (float)j;

            // current candidates become next step's target row
            Pv = Sv[s];

            // refill slot s for step t-4 (addresses path-independent)
            int tc = t - 4; if (tc < 0) tc = 0;
            const float* Srow = Sbase + (size_t)tc * NN;
            const float* Frow = Fbase + (size_t)tc * NN;
            Sv[s] = own ? *(const float2*)(Srow + 2 * l) : make_float2(0.f, 0.f);
            Fa[s] = __ldg(Frow + l);
            Fb[s] = __ldg(Frow + 32 + (l & 1));
        }
    }
}

extern "C" void kernel_launch(void* const* d_in, const int* in_sizes, int n_in,
                              void* d_out, int out_size)
{
    const float* feat  = (const float*)d_in[0];
    const float* trans = (const float*)d_in[1];
    if (n_in >= 2 && in_sizes[0] == NN * NN) {
        feat  = (const float*)d_in[1];
        trans = (const float*)d_in[0];
    }
    float* out = (float*)d_out;

    viterbi_fwd<<<FWD_BLOCKS, FWD_THREADS>>>(feat, trans, out);
    viterbi_back<<<BB / 8, 256>>>(feat, trans, out);
}

// round 6
// speedup vs baseline: 2.4355x; 2.4355x over previous
#include <cuda_runtime.h>
#include <cstdint>
#include <cstddef>

#define BB 1024
#define TT 1024
#define NN 34
#define BPB 2                      // batches per block (forward)
#define FWD_THREADS (BPB * NN)     // 68 threads
#define FWD_BLOCKS  592            // 4 CTAs per SM

// Backpointers u8 [b][t][j]; final argmax per batch.
__device__ unsigned char g_bp[(size_t)BB * TT * NN];
__device__ int g_idx[BB];

__device__ __forceinline__ unsigned long long addx2(unsigned long long a, unsigned long long b) {
    unsigned long long r;
    asm("add.rn.f32x2 %0, %1, %2;" : "=l"(r) : "l"(a), "l"(b));
    return r;
}
__device__ __forceinline__ unsigned long long packff(float f) {
    unsigned long long r; unsigned u = __float_as_uint(f);
    asm("mov.b64 %0, {%1, %1};" : "=l"(r) : "r"(u));
    return r;
}
__device__ __forceinline__ void unpk(unsigned long long v, float& lo, float& hi) {
    unsigned a, b;
    asm("mov.b64 {%0, %1}, %2;" : "=r"(a), "=r"(b) : "l"(v));
    lo = __uint_as_float(a); hi = __uint_as_float(b);
}

__global__ __launch_bounds__(FWD_THREADS)
void viterbi_fwd(const float* __restrict__ feat,
                 const float* __restrict__ trans,
                 float* __restrict__ out)
{
    const int tid = threadIdx.x;
    const int bl  = tid / NN;
    const int j   = tid % NN;
    int b = blockIdx.x * BPB + bl;
    if (b >= BB) b = BB - 1;       // tail CTAs duplicate batch 1023: identical writes, benign

    __shared__ __align__(16) float sc[2][BPB][36];
    __shared__ float tend[NN];
    __shared__ float fin[BPB][NN];

    // transition row j packed as f32x2 pairs
    unsigned long long trp[17];
#pragma unroll
    for (int i = 0; i < 17; i++) {
        unsigned lo = __float_as_uint(trans[j * NN + 2 * i]);
        unsigned hi = __float_as_uint(trans[j * NN + 2 * i + 1]);
        asm("mov.b64 %0, {%1, %2};" : "=l"(trp[i]) : "r"(lo), "r"(hi));
    }
    if (tid < NN) tend[tid] = trans[(NN - 1) * NN + tid];

    const float init = (j == NN - 2) ? 0.0f : -6969.0f;
    sc[0][bl][j] = init;
    __syncthreads();

    const size_t fbase = (size_t)b * ((size_t)TT * NN) + j;
    const float* fp = feat + fbase;
    unsigned char* bpp = g_bp + (size_t)b * ((size_t)TT * NN) + j;

    // 4-deep feat prefetch ring
    float fring[4];
#pragma unroll
    for (int u = 0; u < 4; u++) fring[u] = __ldg(fp + (size_t)u * NN);
    fp += (size_t)4 * NN;

    int cur = 0;
#pragma unroll 1
    for (int tb = 0; tb < TT; tb += 4) {
#pragma unroll
        for (int u = 0; u < 4; u++) {
            const int t = tb + u;
            float f = fring[u];
            float fn = 0.0f;
            if (t + 4 < TT) fn = __ldg(fp);
            fp += NN;
            fring[u] = fn;

            const ulonglong2* sp2 = (const ulonglong2*)&sc[cur][bl][0];
            unsigned long long ff = packff(f);

            // candidates c[k] = (score[k] + f) + tr[j][k]  (XLA association)
            float c[NN];
#pragma unroll
            for (int i = 0; i < 8; i++) {
                ulonglong2 q = sp2[i];
                unsigned long long v0 = addx2(addx2(q.x, ff), trp[2 * i]);
                unsigned long long v1 = addx2(addx2(q.y, ff), trp[2 * i + 1]);
                unpk(v0, c[4 * i], c[4 * i + 1]);
                unpk(v1, c[4 * i + 2], c[4 * i + 3]);
            }
            {
                unsigned long long q = *(const unsigned long long*)&sc[cur][bl][32];
                unsigned long long v = addx2(addx2(q, ff), trp[16]);
                unpk(v, c[32], c[33]);
            }

            // exact max tree on a working copy (keeps c[] alive for the bp scan)
            float w[NN];
#pragma unroll
            for (int k = 0; k < NN; k++) w[k] = c[k];
#pragma unroll
            for (int s = 1; s < NN; s <<= 1)
#pragma unroll
                for (int k = 0; k + s < NN; k += (s << 1))
                    w[k] = fmaxf(w[k], w[k + s]);
            const float m0 = w[0];

            // critical chain continues immediately: publish new score
            sc[cur ^ 1][bl][j] = m0;

            // off-chain: backpointer = smallest k with c[k] == m0 (numeric ==,
            // matches jnp.argmax first-occurrence incl. +-0)
            int bp = 33;
#pragma unroll
            for (int k = 32; k >= 0; k--)
                bp = (c[k] == m0) ? k : bp;
            *bpp = (unsigned char)bp;
            bpp += NN;

            cur ^= 1;
            __syncthreads();
        }
    }

    fin[bl][j] = sc[cur][bl][j] + tend[j];
    __syncthreads();
    if (j == 0) {
        float bm = -3.4e38f; int bi = 0;
#pragma unroll
        for (int k = 0; k < NN; k++) {
            float v = fin[bl][k];
            if (v > bm) { bm = v; bi = k; }
        }
        out[b] = bm;
        g_idx[b] = bi;
    }
}

// Round-1 chase: stage batch's bp table in smem, thread 0 walks it.
__global__ __launch_bounds__(256)
void viterbi_back(float* __restrict__ out)
{
    __shared__ unsigned char bp[TT * NN];    // 34816 B
    const int b = blockIdx.x;

    const uint4* src = (const uint4*)(g_bp + (size_t)b * ((size_t)TT * NN));
    uint4* dst = (uint4*)bp;
    for (int i = threadIdx.x; i < (TT * NN) / 16; i += 256) dst[i] = src[i];
    __syncthreads();

    if (threadIdx.x == 0) {
        int i = g_idx[b];
        float* path = out + BB + (size_t)b * (TT + 1);
        path[TT] = (float)i;
        for (int t = TT - 1; t >= 0; t--) {
            i = bp[t * NN + i];
            path[t] = (float)i;
        }
    }
}

extern "C" void kernel_launch(void* const* d_in, const int* in_sizes, int n_in,
                              void* d_out, int out_size)
{
    const float* feat  = (const float*)d_in[0];
    const float* trans = (const float*)d_in[1];
    if (n_in >= 2 && in_sizes[0] == NN * NN) {
        feat  = (const float*)d_in[1];
        trans = (const float*)d_in[0];
    }
    float* out = (float*)d_out;

    viterbi_fwd<<<FWD_BLOCKS, FWD_THREADS>>>(feat, trans, out);
    viterbi_back<<<BB, 256>>>(out);
}